// round 3
// baseline (speedup 1.0000x reference)
#include <cuda_runtime.h>
#include <math.h>

// ---------------------------------------------------------------------------
// Net_5488968204310: single-head self-attention (D=128) + GateNet
//   B=32, N=1024, D=128, fp32
// Round 2: all-static-smem SIMT fp32 pipeline (no dynamic smem, no
// cudaFuncSetAttribute). Scratch in __device__ globals.
// ---------------------------------------------------------------------------

#define B_ 32
#define N_ 1024
#define D_ 128
#define MTOT (B_ * N_)            // 32768 rows

// ---------------- scratch (allocation-free: device globals) ----------------
__device__ float g_q   [(size_t)MTOT * D_];
__device__ float g_k   [(size_t)MTOT * D_];
__device__ float g_v   [(size_t)MTOT * D_];
__device__ float g_attn[(size_t)MTOT * D_];
__device__ float g_msg [(size_t)MTOT * D_];
__device__ float g_ret [(size_t)MTOT * D_];
__device__ float g_t1  [(size_t)MTOT * D_];
__device__ float g_gp  [(size_t)MTOT * D_];
__device__ float g_logits[(size_t)B_ * N_ * N_];   // 128 MB

// ---------------------------------------------------------------------------
// Generic GEMM: C[M,128] = A[M,128] @ W[128,128]  (+ epilogue variants)
//   BM=64, A tile resident (full K), W streamed in 4 K-chunks of 32.
//   256 threads, thread tile 4x8. Static smem: 32KB + 16KB = 48KB.
//   EPI 0: out = acc + bias
//   EPI 1: out = acc + bias + add1
//   EPI 2: out = relu(acc + bias + add1)
//   EPI 3: g = sigmoid(acc + bias); out = add1*g + add2*(1-g)
// ---------------------------------------------------------------------------
template <int EPI>
__global__ __launch_bounds__(256) void gemm128(
    const float* __restrict__ A, const float* __restrict__ W,
    const float* __restrict__ bias,
    const float* __restrict__ add1, const float* __restrict__ add2,
    float* __restrict__ out)
{
    __shared__ float As[64 * 128];   // 32 KB
    __shared__ float Ws[32 * 128];   // 16 KB (one K-chunk of W)

    const int tid = threadIdx.x;
    const long rowblk = (long)blockIdx.x * 64;

    // load A tile (64x128 = 2048 float4, 8 per thread)
    const float4* A4 = (const float4*)(A + rowblk * D_);
    float4* As4 = (float4*)As;
#pragma unroll
    for (int i = 0; i < 8; i++) As4[tid + i * 256] = A4[tid + i * 256];

    const int tx = tid & 15, ty = tid >> 4;
    const int r0 = ty * 4, c0 = tx * 8;

    float acc[4][8];
#pragma unroll
    for (int r = 0; r < 4; r++)
#pragma unroll
        for (int c = 0; c < 8; c++) acc[r][c] = 0.f;

    for (int kc = 0; kc < 4; kc++) {
        __syncthreads();   // As ready (kc==0) / Ws consumed (kc>0)
        // load W chunk: rows [kc*32, kc*32+32) -> 1024 float4, 4 per thread
        const float4* W4 = (const float4*)(W + (long)kc * 32 * 128);
        float4* Ws4 = (float4*)Ws;
#pragma unroll
        for (int i = 0; i < 4; i++) Ws4[tid + i * 256] = W4[tid + i * 256];
        __syncthreads();

#pragma unroll
        for (int kk = 0; kk < 32; kk++) {
            const int kg = kc * 32 + kk;
            float a[4];
#pragma unroll
            for (int r = 0; r < 4; r++) a[r] = As[(r0 + r) * 128 + kg];
            float4 w0 = *(const float4*)&Ws[kk * 128 + c0];
            float4 w1 = *(const float4*)&Ws[kk * 128 + c0 + 4];
            float w[8] = {w0.x, w0.y, w0.z, w0.w, w1.x, w1.y, w1.z, w1.w};
#pragma unroll
            for (int r = 0; r < 4; r++)
#pragma unroll
                for (int c = 0; c < 8; c++)
                    acc[r][c] = fmaf(a[r], w[c], acc[r][c]);
        }
    }

#pragma unroll
    for (int r = 0; r < 4; r++) {
        long row = rowblk + r0 + r;
#pragma unroll
        for (int c = 0; c < 8; c++) {
            int col = c0 + c;
            long idx = row * D_ + col;
            float vv = acc[r][c] + bias[col];
            if constexpr (EPI == 1) {
                vv += add1[idx];
            } else if constexpr (EPI == 2) {
                vv = fmaxf(vv + add1[idx], 0.f);
            } else if constexpr (EPI == 3) {
                float g = 1.f / (1.f + __expf(-vv));
                vv = add1[idx] * g + add2[idx] * (1.f - g);
            }
            out[idx] = vv;
        }
    }
}

// ---------------------------------------------------------------------------
// logits[b,i,j] = dot(q[b,i,:], k[b,j,:]) / sqrt(128)
//   BM=BN=64, K in 2 chunks of 64. 256 threads, thread tile 4x4.
//   Static smem: 2 * 64*65*4 = 33.3 KB. Pitch 65 -> 2-way max conflicts.
// ---------------------------------------------------------------------------
#define LOG_LD 65

__global__ __launch_bounds__(256) void logits_kernel(
    const float* __restrict__ q, const float* __restrict__ k,
    float* __restrict__ out)
{
    __shared__ float Qs[64 * LOG_LD];
    __shared__ float Ks[64 * LOG_LD];

    const int tid = threadIdx.x;
    const int b = blockIdx.z;
    const float* qb = q + ((long)b * N_ + blockIdx.y * 64) * D_;
    const float* kb = k + ((long)b * N_ + blockIdx.x * 64) * D_;

    const int tx = tid & 15, ty = tid >> 4;
    const int i0 = ty * 4, j0 = tx * 4;

    float acc[4][4];
#pragma unroll
    for (int r = 0; r < 4; r++)
#pragma unroll
        for (int c = 0; c < 4; c++) acc[r][c] = 0.f;

    for (int kc = 0; kc < 2; kc++) {
        __syncthreads();
        // load 64x64 chunk of q and k: 1024 float4 each, 4 per thread
#pragma unroll
        for (int i = 0; i < 4; i++) {
            int idx = tid + i * 256;       // 0..1023
            int row = idx >> 4;            // 16 float4 per 64-float row
            int c4 = idx & 15;
            float4 qv = *(const float4*)&qb[(long)row * D_ + kc * 64 + c4 * 4];
            float4 kv = *(const float4*)&kb[(long)row * D_ + kc * 64 + c4 * 4];
            float* dq = &Qs[row * LOG_LD + c4 * 4];
            dq[0] = qv.x; dq[1] = qv.y; dq[2] = qv.z; dq[3] = qv.w;
            float* dk = &Ks[row * LOG_LD + c4 * 4];
            dk[0] = kv.x; dk[1] = kv.y; dk[2] = kv.z; dk[3] = kv.w;
        }
        __syncthreads();

#pragma unroll
        for (int kk = 0; kk < 64; kk++) {
            float a[4], bb[4];
#pragma unroll
            for (int r = 0; r < 4; r++) a[r] = Qs[(i0 + r) * LOG_LD + kk];
#pragma unroll
            for (int c = 0; c < 4; c++) bb[c] = Ks[(j0 + c) * LOG_LD + kk];
#pragma unroll
            for (int r = 0; r < 4; r++)
#pragma unroll
                for (int c = 0; c < 4; c++)
                    acc[r][c] = fmaf(a[r], bb[c], acc[r][c]);
        }
    }

    const float scale = 0.08838834764831845f;  // 1/sqrt(128)
    const long obase =
        ((long)b * N_ + blockIdx.y * 64 + i0) * N_ + blockIdx.x * 64 + j0;
#pragma unroll
    for (int r = 0; r < 4; r++)
#pragma unroll
        for (int c = 0; c < 4; c++)
            out[obase + (long)r * N_ + c] = acc[r][c] * scale;
}

// ---------------------------------------------------------------------------
// Row softmax over 1024 cols, in place. One block per row, 256 thr, float4.
// ---------------------------------------------------------------------------
__global__ __launch_bounds__(256) void softmax_kernel(float* __restrict__ L)
{
    __shared__ float smax[8], ssum[8];
    const long row = blockIdx.x;
    float4* p = (float4*)L + row * 256 + threadIdx.x;
    float4 v = *p;

    float m = fmaxf(fmaxf(v.x, v.y), fmaxf(v.z, v.w));
#pragma unroll
    for (int o = 16; o; o >>= 1) m = fmaxf(m, __shfl_xor_sync(0xffffffffu, m, o));
    const int warp = threadIdx.x >> 5, lane = threadIdx.x & 31;
    if (!lane) smax[warp] = m;
    __syncthreads();
    float rm = fmaxf(fmaxf(fmaxf(smax[0], smax[1]), fmaxf(smax[2], smax[3])),
                     fmaxf(fmaxf(smax[4], smax[5]), fmaxf(smax[6], smax[7])));

    v.x = __expf(v.x - rm);
    v.y = __expf(v.y - rm);
    v.z = __expf(v.z - rm);
    v.w = __expf(v.w - rm);
    float s = v.x + v.y + v.z + v.w;
#pragma unroll
    for (int o = 16; o; o >>= 1) s += __shfl_xor_sync(0xffffffffu, s, o);
    if (!lane) ssum[warp] = s;
    __syncthreads();
    float tot = ((ssum[0] + ssum[1]) + (ssum[2] + ssum[3])) +
                ((ssum[4] + ssum[5]) + (ssum[6] + ssum[7]));
    float inv = 1.f / tot;
    v.x *= inv; v.y *= inv; v.z *= inv; v.w *= inv;
    *p = v;
}

// ---------------------------------------------------------------------------
// attn[b,i,d] = sum_j P[b,i,j] * v[b,j,d]
//   BM=64 (i), BN=128 (d), BK=32 (j). 256 threads, thread tile 4x8.
//   Static smem: 8.4 KB + 16.9 KB = 25.3 KB.
// ---------------------------------------------------------------------------
#define AO_LDP 33
#define AO_LDV 132

__global__ __launch_bounds__(256) void attnout_kernel(
    const float* __restrict__ P, const float* __restrict__ V,
    float* __restrict__ out)
{
    __shared__ float Ps[64 * AO_LDP];   // [i][jj]
    __shared__ float Vs[32 * AO_LDV];   // [jj][d]

    const int tid = threadIdx.x;
    const int b = blockIdx.y;
    const int iblk = blockIdx.x * 64;
    const float* Pb = P + ((long)b * N_ + iblk) * N_;
    const float* Vb = V + (long)b * N_ * D_;

    const int tx = tid & 15, ty = tid >> 4;
    const int r0 = ty * 4, c0 = tx * 8;

    float acc[4][8];
#pragma unroll
    for (int r = 0; r < 4; r++)
#pragma unroll
        for (int c = 0; c < 8; c++) acc[r][c] = 0.f;

    for (int jt = 0; jt < 32; jt++) {
        // P tile: 64 x 32 = 512 float4, 2 per thread (scalar smem store, ld=33)
#pragma unroll
        for (int i = 0; i < 2; i++) {
            int idx = tid + i * 256;       // 0..511
            int row = idx >> 3, c4 = idx & 7;
            float4 pv = *(const float4*)&Pb[(long)row * N_ + jt * 32 + c4 * 4];
            float* d = &Ps[row * AO_LDP + c4 * 4];
            d[0] = pv.x; d[1] = pv.y; d[2] = pv.z; d[3] = pv.w;
        }
        // V tile: 32 x 128 = 1024 float4, 4 per thread
        const float4* V4 = (const float4*)(Vb + (long)(jt * 32) * D_);
#pragma unroll
        for (int i = 0; i < 4; i++) {
            int idx = tid + i * 256;       // 0..1023
            int row = idx >> 5, c4 = idx & 31;
            *(float4*)&Vs[row * AO_LDV + c4 * 4] = V4[idx];
        }
        __syncthreads();

#pragma unroll
        for (int jj = 0; jj < 32; jj++) {
            float a[4];
#pragma unroll
            for (int r = 0; r < 4; r++) a[r] = Ps[(r0 + r) * AO_LDP + jj];
            float4 w0 = *(const float4*)&Vs[jj * AO_LDV + c0];
            float4 w1 = *(const float4*)&Vs[jj * AO_LDV + c0 + 4];
            float w[8] = {w0.x, w0.y, w0.z, w0.w, w1.x, w1.y, w1.z, w1.w};
#pragma unroll
            for (int r = 0; r < 4; r++)
#pragma unroll
                for (int c = 0; c < 8; c++)
                    acc[r][c] = fmaf(a[r], w[c], acc[r][c]);
        }
        __syncthreads();
    }

#pragma unroll
    for (int r = 0; r < 4; r++) {
        long row = (long)b * N_ + iblk + r0 + r;
#pragma unroll
        for (int c = 0; c < 8; c++)
            out[row * D_ + c0 + c] = acc[r][c];
    }
}

// ---------------------------------------------------------------------------
extern "C" void kernel_launch(void* const* d_in, const int* in_sizes, int n_in,
                              void* d_out, int out_size)
{
    const float* x   = (const float*)d_in[0];
    const float* Wq  = (const float*)d_in[1];
    const float* bq  = (const float*)d_in[2];
    const float* Wk  = (const float*)d_in[3];
    const float* bk  = (const float*)d_in[4];
    const float* Wv  = (const float*)d_in[5];
    const float* bv  = (const float*)d_in[6];
    const float* Wo  = (const float*)d_in[7];
    const float* bo  = (const float*)d_in[8];
    const float* Wo1 = (const float*)d_in[9];
    const float* bo1 = (const float*)d_in[10];
    const float* Wg1 = (const float*)d_in[11];
    const float* bg1 = (const float*)d_in[12];
    const float* Wg2 = (const float*)d_in[13];
    const float* bg2 = (const float*)d_in[14];
    const float* Wg3 = (const float*)d_in[15];
    const float* bg3 = (const float*)d_in[16];
    float* out = (float*)d_out;

    float *q, *k, *v, *attn, *msg, *ret, *t1, *gp, *logits;
    cudaGetSymbolAddress((void**)&q,    g_q);
    cudaGetSymbolAddress((void**)&k,    g_k);
    cudaGetSymbolAddress((void**)&v,    g_v);
    cudaGetSymbolAddress((void**)&attn, g_attn);
    cudaGetSymbolAddress((void**)&msg,  g_msg);
    cudaGetSymbolAddress((void**)&ret,  g_ret);
    cudaGetSymbolAddress((void**)&t1,   g_t1);
    cudaGetSymbolAddress((void**)&gp,   g_gp);
    cudaGetSymbolAddress((void**)&logits, g_logits);

    const dim3 blk(256);
    const int gemm_blocks = MTOT / 64;   // 512

    // projections
    gemm128<0><<<gemm_blocks, blk>>>(x, Wq, bq, nullptr, nullptr, q);
    gemm128<0><<<gemm_blocks, blk>>>(x, Wk, bk, nullptr, nullptr, k);
    gemm128<0><<<gemm_blocks, blk>>>(x, Wv, bv, nullptr, nullptr, v);

    // attention
    logits_kernel<<<dim3(16, 16, B_), blk>>>(q, k, logits);
    softmax_kernel<<<MTOT, blk>>>(logits);
    attnout_kernel<<<dim3(16, B_), blk>>>(logits, v, attn);

    // output projection + GateNet
    gemm128<0><<<gemm_blocks, blk>>>(attn, Wo, bo, nullptr, nullptr, msg);
    gemm128<1><<<gemm_blocks, blk>>>(x, Wo1, bo1, msg, nullptr, ret);
    gemm128<0><<<gemm_blocks, blk>>>(x, Wg1, bg1, nullptr, nullptr, t1);
    gemm128<2><<<gemm_blocks, blk>>>(msg, Wg2, bg2, t1, nullptr, gp);
    gemm128<3><<<gemm_blocks, blk>>>(gp, Wg3, bg3, ret, x, out);
}

// round 4
// speedup vs baseline: 1.0000x; 1.0000x over previous
#include <cuda_runtime.h>
#include <math.h>

// ---------------------------------------------------------------------------
// Net_5488968204310: single-head self-attention (D=128) + GateNet
//   B=32, N=1024, D=128, fp32
// Round 2: all-static-smem SIMT fp32 pipeline (no dynamic smem, no
// cudaFuncSetAttribute). Scratch in __device__ globals.
// ---------------------------------------------------------------------------

#define B_ 32
#define N_ 1024
#define D_ 128
#define MTOT (B_ * N_)            // 32768 rows

// ---------------- scratch (allocation-free: device globals) ----------------
__device__ float g_q   [(size_t)MTOT * D_];
__device__ float g_k   [(size_t)MTOT * D_];
__device__ float g_v   [(size_t)MTOT * D_];
__device__ float g_attn[(size_t)MTOT * D_];
__device__ float g_msg [(size_t)MTOT * D_];
__device__ float g_ret [(size_t)MTOT * D_];
__device__ float g_t1  [(size_t)MTOT * D_];
__device__ float g_gp  [(size_t)MTOT * D_];
__device__ float g_logits[(size_t)B_ * N_ * N_];   // 128 MB

// ---------------------------------------------------------------------------
// Generic GEMM: C[M,128] = A[M,128] @ W[128,128]  (+ epilogue variants)
//   BM=64, A tile resident (full K), W streamed in 4 K-chunks of 32.
//   256 threads, thread tile 4x8. Static smem: 32KB + 16KB = 48KB.
//   EPI 0: out = acc + bias
//   EPI 1: out = acc + bias + add1
//   EPI 2: out = relu(acc + bias + add1)
//   EPI 3: g = sigmoid(acc + bias); out = add1*g + add2*(1-g)
// ---------------------------------------------------------------------------
template <int EPI>
__global__ __launch_bounds__(256) void gemm128(
    const float* __restrict__ A, const float* __restrict__ W,
    const float* __restrict__ bias,
    const float* __restrict__ add1, const float* __restrict__ add2,
    float* __restrict__ out)
{
    __shared__ float As[64 * 128];   // 32 KB
    __shared__ float Ws[32 * 128];   // 16 KB (one K-chunk of W)

    const int tid = threadIdx.x;
    const long rowblk = (long)blockIdx.x * 64;

    // load A tile (64x128 = 2048 float4, 8 per thread)
    const float4* A4 = (const float4*)(A + rowblk * D_);
    float4* As4 = (float4*)As;
#pragma unroll
    for (int i = 0; i < 8; i++) As4[tid + i * 256] = A4[tid + i * 256];

    const int tx = tid & 15, ty = tid >> 4;
    const int r0 = ty * 4, c0 = tx * 8;

    float acc[4][8];
#pragma unroll
    for (int r = 0; r < 4; r++)
#pragma unroll
        for (int c = 0; c < 8; c++) acc[r][c] = 0.f;

    for (int kc = 0; kc < 4; kc++) {
        __syncthreads();   // As ready (kc==0) / Ws consumed (kc>0)
        // load W chunk: rows [kc*32, kc*32+32) -> 1024 float4, 4 per thread
        const float4* W4 = (const float4*)(W + (long)kc * 32 * 128);
        float4* Ws4 = (float4*)Ws;
#pragma unroll
        for (int i = 0; i < 4; i++) Ws4[tid + i * 256] = W4[tid + i * 256];
        __syncthreads();

#pragma unroll
        for (int kk = 0; kk < 32; kk++) {
            const int kg = kc * 32 + kk;
            float a[4];
#pragma unroll
            for (int r = 0; r < 4; r++) a[r] = As[(r0 + r) * 128 + kg];
            float4 w0 = *(const float4*)&Ws[kk * 128 + c0];
            float4 w1 = *(const float4*)&Ws[kk * 128 + c0 + 4];
            float w[8] = {w0.x, w0.y, w0.z, w0.w, w1.x, w1.y, w1.z, w1.w};
#pragma unroll
            for (int r = 0; r < 4; r++)
#pragma unroll
                for (int c = 0; c < 8; c++)
                    acc[r][c] = fmaf(a[r], w[c], acc[r][c]);
        }
    }

#pragma unroll
    for (int r = 0; r < 4; r++) {
        long row = rowblk + r0 + r;
#pragma unroll
        for (int c = 0; c < 8; c++) {
            int col = c0 + c;
            long idx = row * D_ + col;
            float vv = acc[r][c] + bias[col];
            if constexpr (EPI == 1) {
                vv += add1[idx];
            } else if constexpr (EPI == 2) {
                vv = fmaxf(vv + add1[idx], 0.f);
            } else if constexpr (EPI == 3) {
                float g = 1.f / (1.f + __expf(-vv));
                vv = add1[idx] * g + add2[idx] * (1.f - g);
            }
            out[idx] = vv;
        }
    }
}

// ---------------------------------------------------------------------------
// logits[b,i,j] = dot(q[b,i,:], k[b,j,:]) / sqrt(128)
//   BM=BN=64, K in 2 chunks of 64. 256 threads, thread tile 4x4.
//   Static smem: 2 * 64*65*4 = 33.3 KB. Pitch 65 -> 2-way max conflicts.
// ---------------------------------------------------------------------------
#define LOG_LD 65

__global__ __launch_bounds__(256) void logits_kernel(
    const float* __restrict__ q, const float* __restrict__ k,
    float* __restrict__ out)
{
    __shared__ float Qs[64 * LOG_LD];
    __shared__ float Ks[64 * LOG_LD];

    const int tid = threadIdx.x;
    const int b = blockIdx.z;
    const float* qb = q + ((long)b * N_ + blockIdx.y * 64) * D_;
    const float* kb = k + ((long)b * N_ + blockIdx.x * 64) * D_;

    const int tx = tid & 15, ty = tid >> 4;
    const int i0 = ty * 4, j0 = tx * 4;

    float acc[4][4];
#pragma unroll
    for (int r = 0; r < 4; r++)
#pragma unroll
        for (int c = 0; c < 4; c++) acc[r][c] = 0.f;

    for (int kc = 0; kc < 2; kc++) {
        __syncthreads();
        // load 64x64 chunk of q and k: 1024 float4 each, 4 per thread
#pragma unroll
        for (int i = 0; i < 4; i++) {
            int idx = tid + i * 256;       // 0..1023
            int row = idx >> 4;            // 16 float4 per 64-float row
            int c4 = idx & 15;
            float4 qv = *(const float4*)&qb[(long)row * D_ + kc * 64 + c4 * 4];
            float4 kv = *(const float4*)&kb[(long)row * D_ + kc * 64 + c4 * 4];
            float* dq = &Qs[row * LOG_LD + c4 * 4];
            dq[0] = qv.x; dq[1] = qv.y; dq[2] = qv.z; dq[3] = qv.w;
            float* dk = &Ks[row * LOG_LD + c4 * 4];
            dk[0] = kv.x; dk[1] = kv.y; dk[2] = kv.z; dk[3] = kv.w;
        }
        __syncthreads();

#pragma unroll
        for (int kk = 0; kk < 64; kk++) {
            float a[4], bb[4];
#pragma unroll
            for (int r = 0; r < 4; r++) a[r] = Qs[(i0 + r) * LOG_LD + kk];
#pragma unroll
            for (int c = 0; c < 4; c++) bb[c] = Ks[(j0 + c) * LOG_LD + kk];
#pragma unroll
            for (int r = 0; r < 4; r++)
#pragma unroll
                for (int c = 0; c < 4; c++)
                    acc[r][c] = fmaf(a[r], bb[c], acc[r][c]);
        }
    }

    const float scale = 0.08838834764831845f;  // 1/sqrt(128)
    const long obase =
        ((long)b * N_ + blockIdx.y * 64 + i0) * N_ + blockIdx.x * 64 + j0;
#pragma unroll
    for (int r = 0; r < 4; r++)
#pragma unroll
        for (int c = 0; c < 4; c++)
            out[obase + (long)r * N_ + c] = acc[r][c] * scale;
}

// ---------------------------------------------------------------------------
// Row softmax over 1024 cols, in place. One block per row, 256 thr, float4.
// ---------------------------------------------------------------------------
__global__ __launch_bounds__(256) void softmax_kernel(float* __restrict__ L)
{
    __shared__ float smax[8], ssum[8];
    const long row = blockIdx.x;
    float4* p = (float4*)L + row * 256 + threadIdx.x;
    float4 v = *p;

    float m = fmaxf(fmaxf(v.x, v.y), fmaxf(v.z, v.w));
#pragma unroll
    for (int o = 16; o; o >>= 1) m = fmaxf(m, __shfl_xor_sync(0xffffffffu, m, o));
    const int warp = threadIdx.x >> 5, lane = threadIdx.x & 31;
    if (!lane) smax[warp] = m;
    __syncthreads();
    float rm = fmaxf(fmaxf(fmaxf(smax[0], smax[1]), fmaxf(smax[2], smax[3])),
                     fmaxf(fmaxf(smax[4], smax[5]), fmaxf(smax[6], smax[7])));

    v.x = __expf(v.x - rm);
    v.y = __expf(v.y - rm);
    v.z = __expf(v.z - rm);
    v.w = __expf(v.w - rm);
    float s = v.x + v.y + v.z + v.w;
#pragma unroll
    for (int o = 16; o; o >>= 1) s += __shfl_xor_sync(0xffffffffu, s, o);
    if (!lane) ssum[warp] = s;
    __syncthreads();
    float tot = ((ssum[0] + ssum[1]) + (ssum[2] + ssum[3])) +
                ((ssum[4] + ssum[5]) + (ssum[6] + ssum[7]));
    float inv = 1.f / tot;
    v.x *= inv; v.y *= inv; v.z *= inv; v.w *= inv;
    *p = v;
}

// ---------------------------------------------------------------------------
// attn[b,i,d] = sum_j P[b,i,j] * v[b,j,d]
//   BM=64 (i), BN=128 (d), BK=32 (j). 256 threads, thread tile 4x8.
//   Static smem: 8.4 KB + 16.9 KB = 25.3 KB.
// ---------------------------------------------------------------------------
#define AO_LDP 33
#define AO_LDV 132

__global__ __launch_bounds__(256) void attnout_kernel(
    const float* __restrict__ P, const float* __restrict__ V,
    float* __restrict__ out)
{
    __shared__ float Ps[64 * AO_LDP];   // [i][jj]
    __shared__ float Vs[32 * AO_LDV];   // [jj][d]

    const int tid = threadIdx.x;
    const int b = blockIdx.y;
    const int iblk = blockIdx.x * 64;
    const float* Pb = P + ((long)b * N_ + iblk) * N_;
    const float* Vb = V + (long)b * N_ * D_;

    const int tx = tid & 15, ty = tid >> 4;
    const int r0 = ty * 4, c0 = tx * 8;

    float acc[4][8];
#pragma unroll
    for (int r = 0; r < 4; r++)
#pragma unroll
        for (int c = 0; c < 8; c++) acc[r][c] = 0.f;

    for (int jt = 0; jt < 32; jt++) {
        // P tile: 64 x 32 = 512 float4, 2 per thread (scalar smem store, ld=33)
#pragma unroll
        for (int i = 0; i < 2; i++) {
            int idx = tid + i * 256;       // 0..511
            int row = idx >> 3, c4 = idx & 7;
            float4 pv = *(const float4*)&Pb[(long)row * N_ + jt * 32 + c4 * 4];
            float* d = &Ps[row * AO_LDP + c4 * 4];
            d[0] = pv.x; d[1] = pv.y; d[2] = pv.z; d[3] = pv.w;
        }
        // V tile: 32 x 128 = 1024 float4, 4 per thread
        const float4* V4 = (const float4*)(Vb + (long)(jt * 32) * D_);
#pragma unroll
        for (int i = 0; i < 4; i++) {
            int idx = tid + i * 256;       // 0..1023
            int row = idx >> 5, c4 = idx & 31;
            *(float4*)&Vs[row * AO_LDV + c4 * 4] = V4[idx];
        }
        __syncthreads();

#pragma unroll
        for (int jj = 0; jj < 32; jj++) {
            float a[4];
#pragma unroll
            for (int r = 0; r < 4; r++) a[r] = Ps[(r0 + r) * AO_LDP + jj];
            float4 w0 = *(const float4*)&Vs[jj * AO_LDV + c0];
            float4 w1 = *(const float4*)&Vs[jj * AO_LDV + c0 + 4];
            float w[8] = {w0.x, w0.y, w0.z, w0.w, w1.x, w1.y, w1.z, w1.w};
#pragma unroll
            for (int r = 0; r < 4; r++)
#pragma unroll
                for (int c = 0; c < 8; c++)
                    acc[r][c] = fmaf(a[r], w[c], acc[r][c]);
        }
        __syncthreads();
    }

#pragma unroll
    for (int r = 0; r < 4; r++) {
        long row = (long)b * N_ + iblk + r0 + r;
#pragma unroll
        for (int c = 0; c < 8; c++)
            out[row * D_ + c0 + c] = acc[r][c];
    }
}

// ---------------------------------------------------------------------------
extern "C" void kernel_launch(void* const* d_in, const int* in_sizes, int n_in,
                              void* d_out, int out_size)
{
    const float* x   = (const float*)d_in[0];
    const float* Wq  = (const float*)d_in[1];
    const float* bq  = (const float*)d_in[2];
    const float* Wk  = (const float*)d_in[3];
    const float* bk  = (const float*)d_in[4];
    const float* Wv  = (const float*)d_in[5];
    const float* bv  = (const float*)d_in[6];
    const float* Wo  = (const float*)d_in[7];
    const float* bo  = (const float*)d_in[8];
    const float* Wo1 = (const float*)d_in[9];
    const float* bo1 = (const float*)d_in[10];
    const float* Wg1 = (const float*)d_in[11];
    const float* bg1 = (const float*)d_in[12];
    const float* Wg2 = (const float*)d_in[13];
    const float* bg2 = (const float*)d_in[14];
    const float* Wg3 = (const float*)d_in[15];
    const float* bg3 = (const float*)d_in[16];
    float* out = (float*)d_out;

    float *q, *k, *v, *attn, *msg, *ret, *t1, *gp, *logits;
    cudaGetSymbolAddress((void**)&q,    g_q);
    cudaGetSymbolAddress((void**)&k,    g_k);
    cudaGetSymbolAddress((void**)&v,    g_v);
    cudaGetSymbolAddress((void**)&attn, g_attn);
    cudaGetSymbolAddress((void**)&msg,  g_msg);
    cudaGetSymbolAddress((void**)&ret,  g_ret);
    cudaGetSymbolAddress((void**)&t1,   g_t1);
    cudaGetSymbolAddress((void**)&gp,   g_gp);
    cudaGetSymbolAddress((void**)&logits, g_logits);

    const dim3 blk(256);
    const int gemm_blocks = MTOT / 64;   // 512

    // projections
    gemm128<0><<<gemm_blocks, blk>>>(x, Wq, bq, nullptr, nullptr, q);
    gemm128<0><<<gemm_blocks, blk>>>(x, Wk, bk, nullptr, nullptr, k);
    gemm128<0><<<gemm_blocks, blk>>>(x, Wv, bv, nullptr, nullptr, v);

    // attention
    logits_kernel<<<dim3(16, 16, B_), blk>>>(q, k, logits);
    softmax_kernel<<<MTOT, blk>>>(logits);
    attnout_kernel<<<dim3(16, B_), blk>>>(logits, v, attn);

    // output projection + GateNet
    gemm128<0><<<gemm_blocks, blk>>>(attn, Wo, bo, nullptr, nullptr, msg);
    gemm128<1><<<gemm_blocks, blk>>>(x, Wo1, bo1, msg, nullptr, ret);
    gemm128<0><<<gemm_blocks, blk>>>(x, Wg1, bg1, nullptr, nullptr, t1);
    gemm128<2><<<gemm_blocks, blk>>>(msg, Wg2, bg2, t1, nullptr, gp);
    gemm128<3><<<gemm_blocks, blk>>>(gp, Wg3, bg3, ret, x, out);
}

// round 5
// speedup vs baseline: 1.0001x; 1.0000x over previous
#include <cuda_runtime.h>
#include <math.h>

// ---------------------------------------------------------------------------
// Net_5488968204310: single-head self-attention (D=128) + GateNet
//   B=32, N=1024, D=128, fp32
// Round 2: all-static-smem SIMT fp32 pipeline (no dynamic smem, no
// cudaFuncSetAttribute). Scratch in __device__ globals.
// ---------------------------------------------------------------------------

#define B_ 32
#define N_ 1024
#define D_ 128
#define MTOT (B_ * N_)            // 32768 rows

// ---------------- scratch (allocation-free: device globals) ----------------
__device__ float g_q   [(size_t)MTOT * D_];
__device__ float g_k   [(size_t)MTOT * D_];
__device__ float g_v   [(size_t)MTOT * D_];
__device__ float g_attn[(size_t)MTOT * D_];
__device__ float g_msg [(size_t)MTOT * D_];
__device__ float g_ret [(size_t)MTOT * D_];
__device__ float g_t1  [(size_t)MTOT * D_];
__device__ float g_gp  [(size_t)MTOT * D_];
__device__ float g_logits[(size_t)B_ * N_ * N_];   // 128 MB

// ---------------------------------------------------------------------------
// Generic GEMM: C[M,128] = A[M,128] @ W[128,128]  (+ epilogue variants)
//   BM=64, A tile resident (full K), W streamed in 4 K-chunks of 32.
//   256 threads, thread tile 4x8. Static smem: 32KB + 16KB = 48KB.
//   EPI 0: out = acc + bias
//   EPI 1: out = acc + bias + add1
//   EPI 2: out = relu(acc + bias + add1)
//   EPI 3: g = sigmoid(acc + bias); out = add1*g + add2*(1-g)
// ---------------------------------------------------------------------------
template <int EPI>
__global__ __launch_bounds__(256) void gemm128(
    const float* __restrict__ A, const float* __restrict__ W,
    const float* __restrict__ bias,
    const float* __restrict__ add1, const float* __restrict__ add2,
    float* __restrict__ out)
{
    __shared__ float As[64 * 128];   // 32 KB
    __shared__ float Ws[32 * 128];   // 16 KB (one K-chunk of W)

    const int tid = threadIdx.x;
    const long rowblk = (long)blockIdx.x * 64;

    // load A tile (64x128 = 2048 float4, 8 per thread)
    const float4* A4 = (const float4*)(A + rowblk * D_);
    float4* As4 = (float4*)As;
#pragma unroll
    for (int i = 0; i < 8; i++) As4[tid + i * 256] = A4[tid + i * 256];

    const int tx = tid & 15, ty = tid >> 4;
    const int r0 = ty * 4, c0 = tx * 8;

    float acc[4][8];
#pragma unroll
    for (int r = 0; r < 4; r++)
#pragma unroll
        for (int c = 0; c < 8; c++) acc[r][c] = 0.f;

    for (int kc = 0; kc < 4; kc++) {
        __syncthreads();   // As ready (kc==0) / Ws consumed (kc>0)
        // load W chunk: rows [kc*32, kc*32+32) -> 1024 float4, 4 per thread
        const float4* W4 = (const float4*)(W + (long)kc * 32 * 128);
        float4* Ws4 = (float4*)Ws;
#pragma unroll
        for (int i = 0; i < 4; i++) Ws4[tid + i * 256] = W4[tid + i * 256];
        __syncthreads();

#pragma unroll
        for (int kk = 0; kk < 32; kk++) {
            const int kg = kc * 32 + kk;
            float a[4];
#pragma unroll
            for (int r = 0; r < 4; r++) a[r] = As[(r0 + r) * 128 + kg];
            float4 w0 = *(const float4*)&Ws[kk * 128 + c0];
            float4 w1 = *(const float4*)&Ws[kk * 128 + c0 + 4];
            float w[8] = {w0.x, w0.y, w0.z, w0.w, w1.x, w1.y, w1.z, w1.w};
#pragma unroll
            for (int r = 0; r < 4; r++)
#pragma unroll
                for (int c = 0; c < 8; c++)
                    acc[r][c] = fmaf(a[r], w[c], acc[r][c]);
        }
    }

#pragma unroll
    for (int r = 0; r < 4; r++) {
        long row = rowblk + r0 + r;
#pragma unroll
        for (int c = 0; c < 8; c++) {
            int col = c0 + c;
            long idx = row * D_ + col;
            float vv = acc[r][c] + bias[col];
            if constexpr (EPI == 1) {
                vv += add1[idx];
            } else if constexpr (EPI == 2) {
                vv = fmaxf(vv + add1[idx], 0.f);
            } else if constexpr (EPI == 3) {
                float g = 1.f / (1.f + __expf(-vv));
                vv = add1[idx] * g + add2[idx] * (1.f - g);
            }
            out[idx] = vv;
        }
    }
}

// ---------------------------------------------------------------------------
// logits[b,i,j] = dot(q[b,i,:], k[b,j,:]) / sqrt(128)
//   BM=BN=64, K in 2 chunks of 64. 256 threads, thread tile 4x4.
//   Static smem: 2 * 64*65*4 = 33.3 KB. Pitch 65 -> 2-way max conflicts.
// ---------------------------------------------------------------------------
#define LOG_LD 65

__global__ __launch_bounds__(256) void logits_kernel(
    const float* __restrict__ q, const float* __restrict__ k,
    float* __restrict__ out)
{
    __shared__ float Qs[64 * LOG_LD];
    __shared__ float Ks[64 * LOG_LD];

    const int tid = threadIdx.x;
    const int b = blockIdx.z;
    const float* qb = q + ((long)b * N_ + blockIdx.y * 64) * D_;
    const float* kb = k + ((long)b * N_ + blockIdx.x * 64) * D_;

    const int tx = tid & 15, ty = tid >> 4;
    const int i0 = ty * 4, j0 = tx * 4;

    float acc[4][4];
#pragma unroll
    for (int r = 0; r < 4; r++)
#pragma unroll
        for (int c = 0; c < 4; c++) acc[r][c] = 0.f;

    for (int kc = 0; kc < 2; kc++) {
        __syncthreads();
        // load 64x64 chunk of q and k: 1024 float4 each, 4 per thread
#pragma unroll
        for (int i = 0; i < 4; i++) {
            int idx = tid + i * 256;       // 0..1023
            int row = idx >> 4;            // 16 float4 per 64-float row
            int c4 = idx & 15;
            float4 qv = *(const float4*)&qb[(long)row * D_ + kc * 64 + c4 * 4];
            float4 kv = *(const float4*)&kb[(long)row * D_ + kc * 64 + c4 * 4];
            float* dq = &Qs[row * LOG_LD + c4 * 4];
            dq[0] = qv.x; dq[1] = qv.y; dq[2] = qv.z; dq[3] = qv.w;
            float* dk = &Ks[row * LOG_LD + c4 * 4];
            dk[0] = kv.x; dk[1] = kv.y; dk[2] = kv.z; dk[3] = kv.w;
        }
        __syncthreads();

#pragma unroll
        for (int kk = 0; kk < 64; kk++) {
            float a[4], bb[4];
#pragma unroll
            for (int r = 0; r < 4; r++) a[r] = Qs[(i0 + r) * LOG_LD + kk];
#pragma unroll
            for (int c = 0; c < 4; c++) bb[c] = Ks[(j0 + c) * LOG_LD + kk];
#pragma unroll
            for (int r = 0; r < 4; r++)
#pragma unroll
                for (int c = 0; c < 4; c++)
                    acc[r][c] = fmaf(a[r], bb[c], acc[r][c]);
        }
    }

    const float scale = 0.08838834764831845f;  // 1/sqrt(128)
    const long obase =
        ((long)b * N_ + blockIdx.y * 64 + i0) * N_ + blockIdx.x * 64 + j0;
#pragma unroll
    for (int r = 0; r < 4; r++)
#pragma unroll
        for (int c = 0; c < 4; c++)
            out[obase + (long)r * N_ + c] = acc[r][c] * scale;
}

// ---------------------------------------------------------------------------
// Row softmax over 1024 cols, in place. One block per row, 256 thr, float4.
// ---------------------------------------------------------------------------
__global__ __launch_bounds__(256) void softmax_kernel(float* __restrict__ L)
{
    __shared__ float smax[8], ssum[8];
    const long row = blockIdx.x;
    float4* p = (float4*)L + row * 256 + threadIdx.x;
    float4 v = *p;

    float m = fmaxf(fmaxf(v.x, v.y), fmaxf(v.z, v.w));
#pragma unroll
    for (int o = 16; o; o >>= 1) m = fmaxf(m, __shfl_xor_sync(0xffffffffu, m, o));
    const int warp = threadIdx.x >> 5, lane = threadIdx.x & 31;
    if (!lane) smax[warp] = m;
    __syncthreads();
    float rm = fmaxf(fmaxf(fmaxf(smax[0], smax[1]), fmaxf(smax[2], smax[3])),
                     fmaxf(fmaxf(smax[4], smax[5]), fmaxf(smax[6], smax[7])));

    v.x = __expf(v.x - rm);
    v.y = __expf(v.y - rm);
    v.z = __expf(v.z - rm);
    v.w = __expf(v.w - rm);
    float s = v.x + v.y + v.z + v.w;
#pragma unroll
    for (int o = 16; o; o >>= 1) s += __shfl_xor_sync(0xffffffffu, s, o);
    if (!lane) ssum[warp] = s;
    __syncthreads();
    float tot = ((ssum[0] + ssum[1]) + (ssum[2] + ssum[3])) +
                ((ssum[4] + ssum[5]) + (ssum[6] + ssum[7]));
    float inv = 1.f / tot;
    v.x *= inv; v.y *= inv; v.z *= inv; v.w *= inv;
    *p = v;
}

// ---------------------------------------------------------------------------
// attn[b,i,d] = sum_j P[b,i,j] * v[b,j,d]
//   BM=64 (i), BN=128 (d), BK=32 (j). 256 threads, thread tile 4x8.
//   Static smem: 8.4 KB + 16.9 KB = 25.3 KB.
// ---------------------------------------------------------------------------
#define AO_LDP 33
#define AO_LDV 132

__global__ __launch_bounds__(256) void attnout_kernel(
    const float* __restrict__ P, const float* __restrict__ V,
    float* __restrict__ out)
{
    __shared__ float Ps[64 * AO_LDP];   // [i][jj]
    __shared__ float Vs[32 * AO_LDV];   // [jj][d]

    const int tid = threadIdx.x;
    const int b = blockIdx.y;
    const int iblk = blockIdx.x * 64;
    const float* Pb = P + ((long)b * N_ + iblk) * N_;
    const float* Vb = V + (long)b * N_ * D_;

    const int tx = tid & 15, ty = tid >> 4;
    const int r0 = ty * 4, c0 = tx * 8;

    float acc[4][8];
#pragma unroll
    for (int r = 0; r < 4; r++)
#pragma unroll
        for (int c = 0; c < 8; c++) acc[r][c] = 0.f;

    for (int jt = 0; jt < 32; jt++) {
        // P tile: 64 x 32 = 512 float4, 2 per thread (scalar smem store, ld=33)
#pragma unroll
        for (int i = 0; i < 2; i++) {
            int idx = tid + i * 256;       // 0..511
            int row = idx >> 3, c4 = idx & 7;
            float4 pv = *(const float4*)&Pb[(long)row * N_ + jt * 32 + c4 * 4];
            float* d = &Ps[row * AO_LDP + c4 * 4];
            d[0] = pv.x; d[1] = pv.y; d[2] = pv.z; d[3] = pv.w;
        }
        // V tile: 32 x 128 = 1024 float4, 4 per thread
        const float4* V4 = (const float4*)(Vb + (long)(jt * 32) * D_);
#pragma unroll
        for (int i = 0; i < 4; i++) {
            int idx = tid + i * 256;       // 0..1023
            int row = idx >> 5, c4 = idx & 31;
            *(float4*)&Vs[row * AO_LDV + c4 * 4] = V4[idx];
        }
        __syncthreads();

#pragma unroll
        for (int jj = 0; jj < 32; jj++) {
            float a[4];
#pragma unroll
            for (int r = 0; r < 4; r++) a[r] = Ps[(r0 + r) * AO_LDP + jj];
            float4 w0 = *(const float4*)&Vs[jj * AO_LDV + c0];
            float4 w1 = *(const float4*)&Vs[jj * AO_LDV + c0 + 4];
            float w[8] = {w0.x, w0.y, w0.z, w0.w, w1.x, w1.y, w1.z, w1.w};
#pragma unroll
            for (int r = 0; r < 4; r++)
#pragma unroll
                for (int c = 0; c < 8; c++)
                    acc[r][c] = fmaf(a[r], w[c], acc[r][c]);
        }
        __syncthreads();
    }

#pragma unroll
    for (int r = 0; r < 4; r++) {
        long row = (long)b * N_ + iblk + r0 + r;
#pragma unroll
        for (int c = 0; c < 8; c++)
            out[row * D_ + c0 + c] = acc[r][c];
    }
}

// ---------------------------------------------------------------------------
extern "C" void kernel_launch(void* const* d_in, const int* in_sizes, int n_in,
                              void* d_out, int out_size)
{
    const float* x   = (const float*)d_in[0];
    const float* Wq  = (const float*)d_in[1];
    const float* bq  = (const float*)d_in[2];
    const float* Wk  = (const float*)d_in[3];
    const float* bk  = (const float*)d_in[4];
    const float* Wv  = (const float*)d_in[5];
    const float* bv  = (const float*)d_in[6];
    const float* Wo  = (const float*)d_in[7];
    const float* bo  = (const float*)d_in[8];
    const float* Wo1 = (const float*)d_in[9];
    const float* bo1 = (const float*)d_in[10];
    const float* Wg1 = (const float*)d_in[11];
    const float* bg1 = (const float*)d_in[12];
    const float* Wg2 = (const float*)d_in[13];
    const float* bg2 = (const float*)d_in[14];
    const float* Wg3 = (const float*)d_in[15];
    const float* bg3 = (const float*)d_in[16];
    float* out = (float*)d_out;

    float *q, *k, *v, *attn, *msg, *ret, *t1, *gp, *logits;
    cudaGetSymbolAddress((void**)&q,    g_q);
    cudaGetSymbolAddress((void**)&k,    g_k);
    cudaGetSymbolAddress((void**)&v,    g_v);
    cudaGetSymbolAddress((void**)&attn, g_attn);
    cudaGetSymbolAddress((void**)&msg,  g_msg);
    cudaGetSymbolAddress((void**)&ret,  g_ret);
    cudaGetSymbolAddress((void**)&t1,   g_t1);
    cudaGetSymbolAddress((void**)&gp,   g_gp);
    cudaGetSymbolAddress((void**)&logits, g_logits);

    const dim3 blk(256);
    const int gemm_blocks = MTOT / 64;   // 512

    // projections
    gemm128<0><<<gemm_blocks, blk>>>(x, Wq, bq, nullptr, nullptr, q);
    gemm128<0><<<gemm_blocks, blk>>>(x, Wk, bk, nullptr, nullptr, k);
    gemm128<0><<<gemm_blocks, blk>>>(x, Wv, bv, nullptr, nullptr, v);

    // attention
    logits_kernel<<<dim3(16, 16, B_), blk>>>(q, k, logits);
    softmax_kernel<<<MTOT, blk>>>(logits);
    attnout_kernel<<<dim3(16, B_), blk>>>(logits, v, attn);

    // output projection + GateNet
    gemm128<0><<<gemm_blocks, blk>>>(attn, Wo, bo, nullptr, nullptr, msg);
    gemm128<1><<<gemm_blocks, blk>>>(x, Wo1, bo1, msg, nullptr, ret);
    gemm128<0><<<gemm_blocks, blk>>>(x, Wg1, bg1, nullptr, nullptr, t1);
    gemm128<2><<<gemm_blocks, blk>>>(msg, Wg2, bg2, t1, nullptr, gp);
    gemm128<3><<<gemm_blocks, blk>>>(gp, Wg3, bg3, ret, x, out);
}